// round 13
// baseline (speedup 1.0000x reference)
#include <cuda_runtime.h>
#include <cuda_bf16.h>
#include <math.h>

// Problem constants (fixed by the benchmark's setup_inputs)
#define C_CLASSES 16
#define D_DIM     256
#define N_MAX     32768
#define N_TILES   10          // upper-triangle 64x64 tiles of a 256x256 gram
#define LAM   25.0f
#define MU    25.0f
#define NU     1.0f
#define ALPHA 50.0f
#define EPS_V  1e-4f

#define NCHUNK (N_MAX / 32)   // 1024 chunks of 32 rows
#define CVT_BLOCKS NCHUNK
#define KSPLIT 4              // K-dimension split of the gram reduction
#define N_PAIRS 5             // tile pairs per (class, view)

// ---------------- scratch (device globals; no allocation allowed) ----------
__device__ int   g_chunk_hist[NCHUNK][C_CLASSES];
__device__ int   g_chunk_base[NCHUNK][C_CLASSES];
__device__ int   g_rank[N_MAX];                     // (label<<16) | rank
__device__ int   g_counts[C_CLASSES];
__device__ int   g_offsets[C_CLASSES];
__device__ float g_colsum[KSPLIT][2][C_CLASSES][D_DIM];
__device__ float g_gram[KSPLIT][2][C_CLASSES][N_TILES][64 * 64];
__device__ float g_inv_partial[CVT_BLOCKS];
__device__ float g_cov_partial[2 * C_CLASSES * N_TILES];
__device__ __nv_bfloat16 g_xa[N_MAX * D_DIM];       // class-sorted bf16 rows
__device__ __nv_bfloat16 g_xb[N_MAX * D_DIM];

// ---------------- helpers ---------------------------------------------------
__device__ __forceinline__ float block_reduce_256(float v, float* red) {
    int tid = threadIdx.x;
    red[tid] = v;
    __syncthreads();
    #pragma unroll
    for (int s = 128; s > 0; s >>= 1) {
        if (tid < s) red[tid] += red[tid + s];
        __syncthreads();
    }
    float r = red[0];
    __syncthreads();
    return r;
}

__device__ __forceinline__ void ldsm4t(unsigned& r0, unsigned& r1,
                                       unsigned& r2, unsigned& r3,
                                       unsigned addr) {
    asm volatile("ldmatrix.sync.aligned.m8n8.x4.trans.shared.b16 {%0,%1,%2,%3}, [%4];\n"
                 : "=r"(r0), "=r"(r1), "=r"(r2), "=r"(r3) : "r"(addr));
}

__device__ __forceinline__ void mma16816(float* c, unsigned a0, unsigned a1,
                                         unsigned a2, unsigned a3,
                                         unsigned b0, unsigned b1) {
    asm volatile("mma.sync.aligned.m16n8k16.row.col.f32.bf16.bf16.f32 "
                 "{%0,%1,%2,%3}, {%4,%5,%6,%7}, {%8,%9}, {%0,%1,%2,%3};\n"
                 : "+f"(c[0]), "+f"(c[1]), "+f"(c[2]), "+f"(c[3])
                 : "r"(a0), "r"(a1), "r"(a2), "r"(a3), "r"(b0), "r"(b1));
}

__device__ __forceinline__ void cpa16(void* dst, const void* src, bool pred) {
    unsigned d = (unsigned)__cvta_generic_to_shared(dst);
    int sz = pred ? 16 : 0;
    asm volatile("cp.async.cg.shared.global [%0], [%1], 16, %2;\n"
                 :: "r"(d), "l"(src), "r"(sz));
}
__device__ __forceinline__ void cpa_commit() {
    asm volatile("cp.async.commit_group;\n");
}
__device__ __forceinline__ void cpa_wait1() {
    asm volatile("cp.async.wait_group 1;\n");
}

__device__ __forceinline__ unsigned pack_bf162(float x, float y) {
    __nv_bfloat162 h = __floats2bfloat162_rn(x, y);
    return *reinterpret_cast<unsigned*>(&h);
}

// ---------------- K12: fused histogram + rank + two-level scan (1 block) ----
__global__ void __launch_bounds__(1024) k12_fused(const int* __restrict__ labels,
                                                  int N) {
    __shared__ int ssum[32][C_CLASSES];
    __shared__ int sbase[32][C_CLASSES];
    __shared__ int soff[C_CLASSES];
    int tid  = threadIdx.x;
    int lane = tid & 31;
    int warp = tid >> 5;    // 0..31

    // prefetch this warp's 32 chunk-labels (MLP = 32)
    int labs[32];
    #pragma unroll
    for (int k = 0; k < 32; k++) {
        int row = (warp + 32 * k) * 32 + lane;
        labs[k] = (row < N) ? labels[row] : C_CLASSES;
    }
    #pragma unroll
    for (int k = 0; k < 32; k++) {
        int ch = warp + 32 * k;
        int lab = labs[k];
        unsigned mask = __match_any_sync(0xffffffffu, lab);
        int rank = __popc(mask & ((1u << lane) - 1u));
        if (lane < C_CLASSES) g_chunk_hist[ch][lane] = 0;
        __syncwarp();
        if (lab < C_CLASSES) {
            if ((__ffs(mask) - 1) == lane) g_chunk_hist[ch][lab] = __popc(mask);
            g_rank[ch * 32 + lane] = (lab << 16) | rank;
        }
    }
    __syncthreads();

    if (tid < 512) {
        int sb = tid >> 4, c = tid & 15;
        int s = 0;
        #pragma unroll 4
        for (int k = 0; k < 32; k++) s += g_chunk_hist[sb * 32 + k][c];
        ssum[sb][c] = s;
    }
    __syncthreads();
    if (tid < C_CLASSES) {
        int run = 0;
        for (int b = 0; b < 32; b++) { sbase[b][tid] = run; run += ssum[b][tid]; }
        g_counts[tid] = run;
    }
    __syncthreads();
    if (tid == 0) {
        int o = 0;
        for (int c = 0; c < C_CLASSES; c++) {
            soff[c] = o;
            g_offsets[c] = o;
            o += g_counts[c];
        }
    }
    __syncthreads();
    if (tid < 512) {
        int sb = tid >> 4, c = tid & 15;
        int run = soff[c] + sbase[sb][c];
        for (int k = 0; k < 32; k++) {
            int ch = sb * 32 + k;
            g_chunk_base[ch][c] = run;
            run += g_chunk_hist[ch][c];
        }
    }
}

// ---------------- K1b: convert + deterministic sorted scatter + invariance --
__global__ void __launch_bounds__(256) k1b_cvt(const float* __restrict__ za,
                                               const float* __restrict__ zb,
                                               int N) {
    __shared__ float red[256];
    int tid  = threadIdx.x;
    int lane = tid & 31;
    int w    = tid >> 5;
    int chunk = blockIdx.x;

    float s = 0.f;
    #pragma unroll
    for (int i = 0; i < 4; i += 2) {
        int rowA = chunk * 32 + w * 4 + i;
        int rowB = rowA + 1;
        bool vA = rowA < N, vB = rowB < N;

        const float4* paA = (const float4*)(za + (long)rowA * D_DIM);
        const float4* pbA = (const float4*)(zb + (long)rowA * D_DIM);
        const float4* paB = (const float4*)(za + (long)rowB * D_DIM);
        const float4* pbB = (const float4*)(zb + (long)rowB * D_DIM);

        float4 a0A, a1A, b0A, b1A, a0B, a1B, b0B, b1B;
        if (vA) {
            a0A = __ldcs(paA + lane * 2); a1A = __ldcs(paA + lane * 2 + 1);
            b0A = __ldcs(pbA + lane * 2); b1A = __ldcs(pbA + lane * 2 + 1);
        }
        if (vB) {
            a0B = __ldcs(paB + lane * 2); a1B = __ldcs(paB + lane * 2 + 1);
            b0B = __ldcs(pbB + lane * 2); b1B = __ldcs(pbB + lane * 2 + 1);
        }

        if (vA) {
            int lr  = g_rank[rowA];
            int pos = g_chunk_base[chunk][lr >> 16] + (lr & 0xffff);
            float dx = a0A.x - b0A.x, dy = a0A.y - b0A.y,
                  dz = a0A.z - b0A.z, dw = a0A.w - b0A.w;
            s += dx * dx + dy * dy + dz * dz + dw * dw;
            dx = a1A.x - b1A.x; dy = a1A.y - b1A.y;
            dz = a1A.z - b1A.z; dw = a1A.w - b1A.w;
            s += dx * dx + dy * dy + dz * dz + dw * dw;
            uint4 wa, wb;
            wa.x = pack_bf162(a0A.x, a0A.y); wa.y = pack_bf162(a0A.z, a0A.w);
            wa.z = pack_bf162(a1A.x, a1A.y); wa.w = pack_bf162(a1A.z, a1A.w);
            wb.x = pack_bf162(b0A.x, b0A.y); wb.y = pack_bf162(b0A.z, b0A.w);
            wb.z = pack_bf162(b1A.x, b1A.y); wb.w = pack_bf162(b1A.z, b1A.w);
            ((uint4*)(g_xa + (long)pos * D_DIM))[lane] = wa;
            ((uint4*)(g_xb + (long)pos * D_DIM))[lane] = wb;
        }
        if (vB) {
            int lr  = g_rank[rowB];
            int pos = g_chunk_base[chunk][lr >> 16] + (lr & 0xffff);
            float dx = a0B.x - b0B.x, dy = a0B.y - b0B.y,
                  dz = a0B.z - b0B.z, dw = a0B.w - b0B.w;
            s += dx * dx + dy * dy + dz * dz + dw * dw;
            dx = a1B.x - b1B.x; dy = a1B.y - b1B.y;
            dz = a1B.z - b1B.z; dw = a1B.w - b1B.w;
            s += dx * dx + dy * dy + dz * dz + dw * dw;
            uint4 wa, wb;
            wa.x = pack_bf162(a0B.x, a0B.y); wa.y = pack_bf162(a0B.z, a0B.w);
            wa.z = pack_bf162(a1B.x, a1B.y); wa.w = pack_bf162(a1B.z, a1B.w);
            wb.x = pack_bf162(b0B.x, b0B.y); wb.y = pack_bf162(b0B.z, b0B.w);
            wb.z = pack_bf162(b1B.x, b1B.y); wb.w = pack_bf162(b1B.z, b1B.w);
            ((uint4*)(g_xa + (long)pos * D_DIM))[lane] = wa;
            ((uint4*)(g_xb + (long)pos * D_DIM))[lane] = wb;
        }
    }
    s = block_reduce_256(s, red);
    if (tid == 0) g_inv_partial[chunk] = s;
}

// ---------------- K5: bf16 gram, tile-pair blocks, fat warps ----------------
__constant__ int c_ti[N_TILES] = {0,0,0,0,1,1,1,2,2,3};
__constant__ int c_tj[N_TILES] = {0,1,2,3,1,2,3,2,3,3};
__constant__ int p_t0[N_PAIRS] = {0, 2, 4, 7, 6};   // gram id, tile slot 0
__constant__ int p_t1[N_PAIRS] = {1, 3, 5, 8, 9};   // gram id, tile slot 1
__constant__ int p_strips[N_PAIRS][3] = {{0,1,0},{0,2,3},{1,2,0},{2,3,0},{1,3,0}};
__constant__ int p_nstrips[N_PAIRS] = {2, 3, 2, 2, 2};
__constant__ int p_sa[N_PAIRS][2] = {{0,0},{0,0},{0,0},{0,0},{0,1}};
__constant__ int p_sb[N_PAIRS][2] = {{0,1},{1,2},{0,1},{0,1},{1,1}};
__constant__ int p_cs[N_PAIRS] = {1, 0, 0, 1, 0};

#define KCHUNK 32
#define NSTAGE 3

__global__ void __launch_bounds__(128, 4) k5_gram() {
    int bx    = blockIdx.x;
    int pair  = bx % N_PAIRS;
    int slice = bx / N_PAIRS;
    int c = blockIdx.y;
    int v = blockIdx.z;
    const __nv_bfloat16* __restrict__ x = v ? g_xb : g_xa;

    __shared__ __nv_bfloat16 S[3][NSTAGE][KCHUNK][72];

    int n = g_counts[c];
    int lo  = (int)(((long)n * slice) / KSPLIT);
    int hi  = (int)(((long)n * (slice + 1)) / KSPLIT);
    int cnt = hi - lo;
    int base = g_offsets[c] + lo;

    int tid  = threadIdx.x;
    int lane = tid & 31;
    int warp = tid >> 5;        // 0..3
    int slot = warp >> 1;       // tile slot 0/1
    int m_off = (warp & 1) * 32;

    int nstrips = p_nstrips[pair];
    int s0 = p_strips[pair][0], s1 = p_strips[pair][1], s2 = p_strips[pair][2];
    int sa = p_sa[pair][slot];
    int sb = p_sb[pair][slot];

    unsigned sBase = (unsigned)__cvta_generic_to_shared(&S[0][0][0][0]);
    const unsigned SS = KCHUNK * 72 * 2;   // bytes per (strip, stage)
    int a_row = (lane & 7) + ((lane >> 4) & 1) * 8;
    int a_col = m_off + ((lane >> 3) & 1) * 8;
    unsigned aAddr = sBase + (unsigned)(sa * NSTAGE) * SS
                   + (unsigned)(a_row * 72 + a_col) * 2u;
    int b_row = (lane & 7) + ((lane >> 3) & 1) * 8;
    int b_col = ((lane >> 4) & 1) * 8;
    unsigned bAddr = sBase + (unsigned)(sb * NSTAGE) * SS
                   + (unsigned)(b_row * 72 + b_col) * 2u;

    bool docs  = p_cs[pair] != 0;
    int cs_ls  = tid >> 6;
    int cs_col = tid & 63;
    int cs_gs  = p_strips[pair][cs_ls];
    float cs = 0.f;

    int nchunks = (cnt + KCHUNK - 1) / KCHUNK;

    #define ISSUE(ci, st) do {                                              \
        int ntask = nstrips * 256;                                          \
        for (int task = tid; task < ntask; task += 128) {                   \
            int sp  = task >> 8;                                            \
            int w   = task & 255;                                           \
            int kr  = w >> 3;                                               \
            int seg = w & 7;                                                \
            int kk  = (ci) * KCHUNK + kr;                                   \
            bool pv = kk < cnt;                                             \
            int gs  = (sp == 0) ? s0 : ((sp == 1) ? s1 : s2);               \
            cpa16(&S[sp][st][kr][seg * 8],                                  \
                  x + (long)(base + kk) * D_DIM + gs * 64 + seg * 8, pv);   \
        }                                                                   \
    } while (0)

    float acc[2][8][4] = {};   // [m 16-block][n 8-tile][c0..c3]

    ISSUE(0, 0);
    cpa_commit();
    for (int ci = 0; ci < nchunks; ci++) {
        if (ci + 1 < nchunks) {
            int stn = (ci + 1) % NSTAGE;
            ISSUE(ci + 1, stn);
        }
        cpa_commit();
        cpa_wait1();
        __syncthreads();        // single barrier per chunk
        int st = ci % NSTAGE;
        unsigned stOff = (unsigned)st * SS;
        #pragma unroll
        for (int ks = 0; ks < KCHUNK; ks += 16) {
            unsigned off = stOff + (unsigned)(ks * 72) * 2u;
            unsigned a0, a1, a2, a3, a4, a5, a6, a7;
            ldsm4t(a0, a1, a2, a3, aAddr + off);          // m_off..+15
            ldsm4t(a4, a5, a6, a7, aAddr + off + 32u);    // m_off+16..+31
            #pragma unroll
            for (int g = 0; g < 4; g++) {
                unsigned b0, b1, b2, b3;
                ldsm4t(b0, b1, b2, b3, bAddr + off + (unsigned)g * 32u);
                mma16816(acc[0][2 * g],     a0, a1, a2, a3, b0, b1);
                mma16816(acc[0][2 * g + 1], a0, a1, a2, a3, b2, b3);
                mma16816(acc[1][2 * g],     a4, a5, a6, a7, b0, b1);
                mma16816(acc[1][2 * g + 1], a4, a5, a6, a7, b2, b3);
            }
        }
        if (docs) {
            #pragma unroll
            for (int r = 0; r < KCHUNK; r++)
                cs += __bfloat162float(S[cs_ls][st][r][cs_col]);
        }
    }

    // ---- write partial gram tiles ----
    int tgram = slot ? p_t1[pair] : p_t0[pair];
    float* G = g_gram[slice][v][c][tgram];
    int g  = lane >> 2;       // 0..7
    int tg = lane & 3;        // 0..3
    #pragma unroll
    for (int mi = 0; mi < 2; mi++) {
        int r0 = m_off + mi * 16 + g;
        int r1 = r0 + 8;
        #pragma unroll
        for (int nt = 0; nt < 8; nt++) {
            int col = nt * 8 + 2 * tg;
            *(float2*)&G[r0 * 64 + col] = make_float2(acc[mi][nt][0], acc[mi][nt][1]);
            *(float2*)&G[r1 * 64 + col] = make_float2(acc[mi][nt][2], acc[mi][nt][3]);
        }
    }

    // ---- colsum writers (per-thread column sums; no reduction needed) ----
    if (docs)
        g_colsum[slice][v][c][cs_gs * 64 + cs_col] = cs;
}

// ---------------- K5c: covariance partials (means computed inline) ----------
__global__ void __launch_bounds__(256) k5c_cov() {
    int t = blockIdx.x;
    int c = blockIdx.y;
    int v = blockIdx.z;
    int ti = c_ti[t], tj = c_tj[t];
    bool diag = (ti == tj);

    __shared__ float mi[64], mj[64];
    __shared__ float red[256];
    int tid = threadIdx.x;
    float fn = (float)g_counts[c];
    if (tid < 64) {
        float s = 0.f;
        #pragma unroll
        for (int sl = 0; sl < KSPLIT; sl++)
            s += g_colsum[sl][v][c][ti * 64 + tid];
        mi[tid] = s / fn;
    } else if (tid < 128) {
        float s = 0.f;
        #pragma unroll
        for (int sl = 0; sl < KSPLIT; sl++)
            s += g_colsum[sl][v][c][tj * 64 + (tid - 64)];
        mj[tid - 64] = s / fn;
    }
    __syncthreads();

    const float* __restrict__ G0 = g_gram[0][v][c][t];
    const float* __restrict__ G1 = g_gram[1][v][c][t];
    const float* __restrict__ G2 = g_gram[2][v][c][t];
    const float* __restrict__ G3 = g_gram[3][v][c][t];
    float inv_nm1 = 1.f / (fn - 1.f);
    float wgt_tile = diag ? 1.f : 2.f;

    float sum = 0.f;
    #pragma unroll
    for (int k = 0; k < 16; k++) {
        int idx = tid + k * 256;
        int r = idx >> 6, col = idx & 63;
        float cv = (G0[idx] + G1[idx] + G2[idx] + G3[idx]
                    - fn * mi[r] * mj[col]) * inv_nm1;
        float w = (diag && r == col) ? 0.f : wgt_tile;
        sum += w * cv * cv;
    }
    sum = block_reduce_256(sum, red);
    if (tid == 0) g_cov_partial[(v * C_CLASSES + c) * N_TILES + t] = sum;
}

// ---------------- K6: finalize all terms (mean/var on the fly) --------------
__constant__ int c_diagt[4] = {0, 4, 7, 9};

__global__ void k6_final(float* __restrict__ out, int N) {
    __shared__ float m[C_CLASSES * D_DIM];
    __shared__ float red[256];
    int tid = threadIdx.x;

    // mean/var on the fly: entry e = v*4096 + c*256 + d; both views of a
    // given (c,d) land on the same thread (v=0 iterations first).
    float vsum = 0.f;
    for (int e = tid; e < 2 * C_CLASSES * D_DIM; e += 256) {
        int d = e & (D_DIM - 1);
        int c = (e >> 8) & (C_CLASSES - 1);
        int v = e >> 12;
        float fn = (float)g_counts[c];
        float colsum = 0.f, Gdd = 0.f;
        int s = d >> 6, dd = d & 63;
        #pragma unroll
        for (int sl = 0; sl < KSPLIT; sl++) {
            colsum += g_colsum[sl][v][c][d];
            Gdd    += g_gram[sl][v][c][c_diagt[s]][dd * 64 + dd];
        }
        float mean = colsum / fn;
        float var  = (Gdd - fn * mean * mean) / (fn - 1.f);
        vsum += fmaxf(0.f, 1.f - sqrtf(var + EPS_V));
        int mc = c * D_DIM + d;
        if (v == 0) m[mc] = 0.5f * mean;
        else        m[mc] += 0.5f * mean;
    }
    __syncthreads();
    vsum = block_reduce_256(vsum, red);

    // invariance partials
    float inv_sum = 0.f;
    for (int e = tid; e < CVT_BLOCKS; e += 256) inv_sum += g_inv_partial[e];
    inv_sum = block_reduce_256(inv_sum, red);

    // covariance
    float csum = 0.f;
    for (int e = tid; e < 2 * C_CLASSES * N_TILES; e += 256)
        csum += g_cov_partial[e];
    csum = block_reduce_256(csum, red);

    // class-discriminative margin (120 pairs)
    float psum = 0.f;
    const int npairs = C_CLASSES * (C_CLASSES - 1) / 2;
    if (tid < npairs) {
        int i = 0, rem = tid;
        while (rem >= C_CLASSES - 1 - i) { rem -= C_CLASSES - 1 - i; i++; }
        int j = i + 1 + rem;
        float d2 = 0.f;
        for (int d = 0; d < D_DIM; d++) {
            float df = m[i * D_DIM + d] - m[j * D_DIM + d];
            d2 += df * df;
        }
        float dist = sqrtf(d2);
        float rr = fmaxf(0.f, ALPHA - dist);
        psum = rr * rr;
    }
    psum = block_reduce_256(psum, red);

    if (tid == 0) {
        float inv_loss   = inv_sum / ((float)N * (float)D_DIM);
        float var_loss   = vsum * 0.5f / ((float)C_CLASSES * (float)D_DIM);
        float cov_loss   = csum * 0.5f / ((float)C_CLASSES * (float)D_DIM);
        float class_loss = psum / (float)npairs;
        out[0] = LAM * inv_loss + MU * var_loss + NU * cov_loss + ALPHA * class_loss;
    }
}

// ---------------- launch -----------------------------------------------------
extern "C" void kernel_launch(void* const* d_in, const int* in_sizes, int n_in,
                              void* d_out, int out_size) {
    const float* za     = (const float*)d_in[0];
    const float* zb     = (const float*)d_in[1];
    const int*   labels = (const int*)d_in[2];
    int N = in_sizes[2];   // labels element count

    k12_fused<<<1, 1024>>>(labels, N);
    k1b_cvt<<<NCHUNK, 256>>>(za, zb, N);
    k5_gram<<<dim3(N_PAIRS * KSPLIT, C_CLASSES, 2), 128>>>();
    k5c_cov<<<dim3(N_TILES, C_CLASSES, 2), 256>>>();
    k6_final<<<1, 256>>>((float*)d_out, N);
}

// round 14
// speedup vs baseline: 1.2183x; 1.2183x over previous
#include <cuda_runtime.h>
#include <cuda_bf16.h>
#include <math.h>

// Problem constants (fixed by the benchmark's setup_inputs)
#define C_CLASSES 16
#define D_DIM     256
#define N_MAX     32768
#define N_TILES   10          // upper-triangle 64x64 tiles of a 256x256 gram
#define LAM   25.0f
#define MU    25.0f
#define NU     1.0f
#define ALPHA 50.0f
#define EPS_V  1e-4f

#define NCHUNK (N_MAX / 32)   // 1024 chunks of 32 rows
#define CVT_BLOCKS NCHUNK
#define KSPLIT 3              // K-dimension split of the gram reduction
#define N_PAIRS 5             // tile pairs per (class, view)

// ---------------- scratch (device globals; no allocation allowed) ----------
__device__ int   g_chunk_hist[NCHUNK][C_CLASSES];
__device__ int   g_chunk_base[NCHUNK][C_CLASSES];
__device__ int   g_rank[N_MAX];                     // (label<<16) | rank
__device__ int   g_counts[C_CLASSES];
__device__ int   g_offsets[C_CLASSES];
__device__ float g_colsum[KSPLIT][2][C_CLASSES][D_DIM];
__device__ float g_gram[KSPLIT][2][C_CLASSES][N_TILES][64 * 64];
__device__ float g_inv_partial[CVT_BLOCKS];
__device__ float g_cov_partial[2 * C_CLASSES * N_TILES];
__device__ __nv_bfloat16 g_xa[N_MAX * D_DIM];       // class-sorted bf16 rows
__device__ __nv_bfloat16 g_xb[N_MAX * D_DIM];

// ---------------- helpers ---------------------------------------------------
__device__ __forceinline__ float block_reduce_256(float v, float* red) {
    int tid = threadIdx.x;
    red[tid] = v;
    __syncthreads();
    #pragma unroll
    for (int s = 128; s > 0; s >>= 1) {
        if (tid < s) red[tid] += red[tid + s];
        __syncthreads();
    }
    float r = red[0];
    __syncthreads();
    return r;
}

__device__ __forceinline__ void ldsm4t(unsigned& r0, unsigned& r1,
                                       unsigned& r2, unsigned& r3,
                                       unsigned addr) {
    asm volatile("ldmatrix.sync.aligned.m8n8.x4.trans.shared.b16 {%0,%1,%2,%3}, [%4];\n"
                 : "=r"(r0), "=r"(r1), "=r"(r2), "=r"(r3) : "r"(addr));
}

__device__ __forceinline__ void mma16816(float* c, unsigned a0, unsigned a1,
                                         unsigned a2, unsigned a3,
                                         unsigned b0, unsigned b1) {
    asm volatile("mma.sync.aligned.m16n8k16.row.col.f32.bf16.bf16.f32 "
                 "{%0,%1,%2,%3}, {%4,%5,%6,%7}, {%8,%9}, {%0,%1,%2,%3};\n"
                 : "+f"(c[0]), "+f"(c[1]), "+f"(c[2]), "+f"(c[3])
                 : "r"(a0), "r"(a1), "r"(a2), "r"(a3), "r"(b0), "r"(b1));
}

__device__ __forceinline__ void cpa16(void* dst, const void* src, bool pred) {
    unsigned d = (unsigned)__cvta_generic_to_shared(dst);
    int sz = pred ? 16 : 0;
    asm volatile("cp.async.cg.shared.global [%0], [%1], 16, %2;\n"
                 :: "r"(d), "l"(src), "r"(sz));
}
__device__ __forceinline__ void cpa_commit() {
    asm volatile("cp.async.commit_group;\n");
}
__device__ __forceinline__ void cpa_wait1() {
    asm volatile("cp.async.wait_group 1;\n");
}

__device__ __forceinline__ unsigned pack_bf162(float x, float y) {
    __nv_bfloat162 h = __floats2bfloat162_rn(x, y);
    return *reinterpret_cast<unsigned*>(&h);
}

// ---------------- K1: per-chunk histogram + per-row rank (ballot) -----------
__global__ void k1_hist(const int* __restrict__ labels, int N) {
    int lane  = threadIdx.x & 31;
    int chunk = blockIdx.x * 8 + (threadIdx.x >> 5);
    int row   = chunk * 32 + lane;
    int lab   = (row < N) ? labels[row] : C_CLASSES;   // sentinel for OOB
    if (lane < C_CLASSES) g_chunk_hist[chunk][lane] = 0;
    __syncwarp();
    unsigned mask = __match_any_sync(0xffffffffu, lab);
    int rank = __popc(mask & ((1u << lane) - 1u));
    int leader = __ffs(mask) - 1;
    if (lab < C_CLASSES) {
        if (lane == leader) g_chunk_hist[chunk][lab] = __popc(mask);
        g_rank[row] = (lab << 16) | rank;
    }
}

// ---------------- K2: two-level scan -> per-chunk class bases ---------------
__global__ void __launch_bounds__(512) k2_scan() {
    __shared__ int ssum[32][C_CLASSES];
    __shared__ int sbase[32][C_CLASSES];
    __shared__ int soff[C_CLASSES];
    int t = threadIdx.x;          // 0..511
    int sb = t >> 4, c = t & 15;  // superblock 0..31, class 0..15
    int s = 0;
    #pragma unroll 4
    for (int k = 0; k < 32; k++) s += g_chunk_hist[sb * 32 + k][c];
    ssum[sb][c] = s;
    __syncthreads();
    if (t < C_CLASSES) {
        int run = 0;
        for (int b = 0; b < 32; b++) { sbase[b][t] = run; run += ssum[b][t]; }
        g_counts[t] = run;
    }
    __syncthreads();
    if (t == 0) {
        int o = 0;
        for (int cc = 0; cc < C_CLASSES; cc++) {
            soff[cc] = o;
            g_offsets[cc] = o;
            o += g_counts[cc];
        }
    }
    __syncthreads();
    int run = soff[c] + sbase[sb][c];
    for (int k = 0; k < 32; k++) {
        int ch = sb * 32 + k;
        g_chunk_base[ch][c] = run;
        run += g_chunk_hist[ch][c];
    }
}

// ---------------- K1b: convert + deterministic sorted scatter + invariance --
__global__ void __launch_bounds__(256) k1b_cvt(const float* __restrict__ za,
                                               const float* __restrict__ zb,
                                               int N) {
    __shared__ float red[256];
    int tid  = threadIdx.x;
    int lane = tid & 31;
    int w    = tid >> 5;
    int chunk = blockIdx.x;

    float s = 0.f;
    #pragma unroll
    for (int i = 0; i < 4; i += 2) {
        int rowA = chunk * 32 + w * 4 + i;
        int rowB = rowA + 1;
        bool vA = rowA < N, vB = rowB < N;

        const float4* paA = (const float4*)(za + (long)rowA * D_DIM);
        const float4* pbA = (const float4*)(zb + (long)rowA * D_DIM);
        const float4* paB = (const float4*)(za + (long)rowB * D_DIM);
        const float4* pbB = (const float4*)(zb + (long)rowB * D_DIM);

        float4 a0A, a1A, b0A, b1A, a0B, a1B, b0B, b1B;
        if (vA) {
            a0A = __ldcs(paA + lane * 2); a1A = __ldcs(paA + lane * 2 + 1);
            b0A = __ldcs(pbA + lane * 2); b1A = __ldcs(pbA + lane * 2 + 1);
        }
        if (vB) {
            a0B = __ldcs(paB + lane * 2); a1B = __ldcs(paB + lane * 2 + 1);
            b0B = __ldcs(pbB + lane * 2); b1B = __ldcs(pbB + lane * 2 + 1);
        }

        if (vA) {
            int lr  = g_rank[rowA];
            int pos = g_chunk_base[chunk][lr >> 16] + (lr & 0xffff);
            float dx = a0A.x - b0A.x, dy = a0A.y - b0A.y,
                  dz = a0A.z - b0A.z, dw = a0A.w - b0A.w;
            s += dx * dx + dy * dy + dz * dz + dw * dw;
            dx = a1A.x - b1A.x; dy = a1A.y - b1A.y;
            dz = a1A.z - b1A.z; dw = a1A.w - b1A.w;
            s += dx * dx + dy * dy + dz * dz + dw * dw;
            uint4 wa, wb;
            wa.x = pack_bf162(a0A.x, a0A.y); wa.y = pack_bf162(a0A.z, a0A.w);
            wa.z = pack_bf162(a1A.x, a1A.y); wa.w = pack_bf162(a1A.z, a1A.w);
            wb.x = pack_bf162(b0A.x, b0A.y); wb.y = pack_bf162(b0A.z, b0A.w);
            wb.z = pack_bf162(b1A.x, b1A.y); wb.w = pack_bf162(b1A.z, b1A.w);
            ((uint4*)(g_xa + (long)pos * D_DIM))[lane] = wa;
            ((uint4*)(g_xb + (long)pos * D_DIM))[lane] = wb;
        }
        if (vB) {
            int lr  = g_rank[rowB];
            int pos = g_chunk_base[chunk][lr >> 16] + (lr & 0xffff);
            float dx = a0B.x - b0B.x, dy = a0B.y - b0B.y,
                  dz = a0B.z - b0B.z, dw = a0B.w - b0B.w;
            s += dx * dx + dy * dy + dz * dz + dw * dw;
            dx = a1B.x - b1B.x; dy = a1B.y - b1B.y;
            dz = a1B.z - b1B.z; dw = a1B.w - b1B.w;
            s += dx * dx + dy * dy + dz * dz + dw * dw;
            uint4 wa, wb;
            wa.x = pack_bf162(a0B.x, a0B.y); wa.y = pack_bf162(a0B.z, a0B.w);
            wa.z = pack_bf162(a1B.x, a1B.y); wa.w = pack_bf162(a1B.z, a1B.w);
            wb.x = pack_bf162(b0B.x, b0B.y); wb.y = pack_bf162(b0B.z, b0B.w);
            wb.z = pack_bf162(b1B.x, b1B.y); wb.w = pack_bf162(b1B.z, b1B.w);
            ((uint4*)(g_xa + (long)pos * D_DIM))[lane] = wa;
            ((uint4*)(g_xb + (long)pos * D_DIM))[lane] = wb;
        }
    }
    s = block_reduce_256(s, red);
    if (tid == 0) g_inv_partial[chunk] = s;
}

// ---------------- K5: bf16 gram, tile-pair blocks, fat warps ----------------
__constant__ int c_ti[N_TILES] = {0,0,0,0,1,1,1,2,2,3};
__constant__ int c_tj[N_TILES] = {0,1,2,3,1,2,3,2,3,3};
__constant__ int p_t0[N_PAIRS] = {0, 2, 4, 7, 6};   // gram id, tile slot 0
__constant__ int p_t1[N_PAIRS] = {1, 3, 5, 8, 9};   // gram id, tile slot 1
__constant__ int p_strips[N_PAIRS][3] = {{0,1,0},{0,2,3},{1,2,0},{2,3,0},{1,3,0}};
__constant__ int p_nstrips[N_PAIRS] = {2, 3, 2, 2, 2};
__constant__ int p_sa[N_PAIRS][2] = {{0,0},{0,0},{0,0},{0,0},{0,1}};
__constant__ int p_sb[N_PAIRS][2] = {{0,1},{1,2},{0,1},{0,1},{1,1}};
__constant__ int p_cs[N_PAIRS] = {1, 0, 0, 1, 0};

#define KCHUNK 32
#define NSTAGE 3

__global__ void __launch_bounds__(128, 4) k5_gram() {
    int bx    = blockIdx.x;
    int pair  = bx % N_PAIRS;
    int slice = bx / N_PAIRS;
    int c = blockIdx.y;
    int v = blockIdx.z;
    const __nv_bfloat16* __restrict__ x = v ? g_xb : g_xa;

    __shared__ __nv_bfloat16 S[3][NSTAGE][KCHUNK][72];

    int n = g_counts[c];
    int lo  = (int)(((long)n * slice) / KSPLIT);
    int hi  = (int)(((long)n * (slice + 1)) / KSPLIT);
    int cnt = hi - lo;
    int base = g_offsets[c] + lo;

    int tid  = threadIdx.x;
    int lane = tid & 31;
    int warp = tid >> 5;        // 0..3
    int slot = warp >> 1;       // tile slot 0/1
    int m_off = (warp & 1) * 32;

    int nstrips = p_nstrips[pair];
    int s0 = p_strips[pair][0], s1 = p_strips[pair][1], s2 = p_strips[pair][2];
    int sa = p_sa[pair][slot];
    int sb = p_sb[pair][slot];

    unsigned sBase = (unsigned)__cvta_generic_to_shared(&S[0][0][0][0]);
    const unsigned SS = KCHUNK * 72 * 2;   // bytes per (strip, stage)
    int a_row = (lane & 7) + ((lane >> 4) & 1) * 8;
    int a_col = m_off + ((lane >> 3) & 1) * 8;
    unsigned aAddr = sBase + (unsigned)(sa * NSTAGE) * SS
                   + (unsigned)(a_row * 72 + a_col) * 2u;
    int b_row = (lane & 7) + ((lane >> 3) & 1) * 8;
    int b_col = ((lane >> 4) & 1) * 8;
    unsigned bAddr = sBase + (unsigned)(sb * NSTAGE) * SS
                   + (unsigned)(b_row * 72 + b_col) * 2u;

    bool docs  = p_cs[pair] != 0;
    int cs_ls  = tid >> 6;
    int cs_col = tid & 63;
    int cs_gs  = p_strips[pair][cs_ls];
    float cs = 0.f;

    int nchunks = (cnt + KCHUNK - 1) / KCHUNK;

    #define ISSUE(ci, st) do {                                              \
        int ntask = nstrips * 256;                                          \
        for (int task = tid; task < ntask; task += 128) {                   \
            int sp  = task >> 8;                                            \
            int w   = task & 255;                                           \
            int kr  = w >> 3;                                               \
            int seg = w & 7;                                                \
            int kk  = (ci) * KCHUNK + kr;                                   \
            bool pv = kk < cnt;                                             \
            int gs  = (sp == 0) ? s0 : ((sp == 1) ? s1 : s2);               \
            cpa16(&S[sp][st][kr][seg * 8],                                  \
                  x + (long)(base + kk) * D_DIM + gs * 64 + seg * 8, pv);   \
        }                                                                   \
    } while (0)

    float acc[2][8][4] = {};   // [m 16-block][n 8-tile][c0..c3]

    ISSUE(0, 0);
    cpa_commit();
    for (int ci = 0; ci < nchunks; ci++) {
        if (ci + 1 < nchunks) {
            int stn = (ci + 1) % NSTAGE;
            ISSUE(ci + 1, stn);
        }
        cpa_commit();
        cpa_wait1();
        __syncthreads();        // single barrier per chunk
        int st = ci % NSTAGE;
        unsigned stOff = (unsigned)st * SS;
        #pragma unroll
        for (int ks = 0; ks < KCHUNK; ks += 16) {
            unsigned off = stOff + (unsigned)(ks * 72) * 2u;
            unsigned a0, a1, a2, a3, a4, a5, a6, a7;
            ldsm4t(a0, a1, a2, a3, aAddr + off);          // m_off..+15
            ldsm4t(a4, a5, a6, a7, aAddr + off + 32u);    // m_off+16..+31
            #pragma unroll
            for (int g = 0; g < 4; g++) {
                unsigned b0, b1, b2, b3;
                ldsm4t(b0, b1, b2, b3, bAddr + off + (unsigned)g * 32u);
                mma16816(acc[0][2 * g],     a0, a1, a2, a3, b0, b1);
                mma16816(acc[0][2 * g + 1], a0, a1, a2, a3, b2, b3);
                mma16816(acc[1][2 * g],     a4, a5, a6, a7, b0, b1);
                mma16816(acc[1][2 * g + 1], a4, a5, a6, a7, b2, b3);
            }
        }
        if (docs) {
            #pragma unroll
            for (int r = 0; r < KCHUNK; r++)
                cs += __bfloat162float(S[cs_ls][st][r][cs_col]);
        }
    }

    // ---- write partial gram tiles ----
    int tgram = slot ? p_t1[pair] : p_t0[pair];
    float* G = g_gram[slice][v][c][tgram];
    int g  = lane >> 2;       // 0..7
    int tg = lane & 3;        // 0..3
    #pragma unroll
    for (int mi = 0; mi < 2; mi++) {
        int r0 = m_off + mi * 16 + g;
        int r1 = r0 + 8;
        #pragma unroll
        for (int nt = 0; nt < 8; nt++) {
            int col = nt * 8 + 2 * tg;
            *(float2*)&G[r0 * 64 + col] = make_float2(acc[mi][nt][0], acc[mi][nt][1]);
            *(float2*)&G[r1 * 64 + col] = make_float2(acc[mi][nt][2], acc[mi][nt][3]);
        }
    }

    // ---- colsum writers (per-thread column sums; no reduction needed) ----
    if (docs)
        g_colsum[slice][v][c][cs_gs * 64 + cs_col] = cs;
}

// ---------------- K5c: covariance partials (means computed inline) ----------
__global__ void __launch_bounds__(256) k5c_cov() {
    int t = blockIdx.x;
    int c = blockIdx.y;
    int v = blockIdx.z;
    int ti = c_ti[t], tj = c_tj[t];
    bool diag = (ti == tj);

    __shared__ float mi[64], mj[64];
    __shared__ float red[256];
    int tid = threadIdx.x;
    float fn = (float)g_counts[c];
    if (tid < 64) {
        float s = 0.f;
        #pragma unroll
        for (int sl = 0; sl < KSPLIT; sl++)
            s += g_colsum[sl][v][c][ti * 64 + tid];
        mi[tid] = s / fn;
    } else if (tid < 128) {
        float s = 0.f;
        #pragma unroll
        for (int sl = 0; sl < KSPLIT; sl++)
            s += g_colsum[sl][v][c][tj * 64 + (tid - 64)];
        mj[tid - 64] = s / fn;
    }
    __syncthreads();

    const float* __restrict__ G0 = g_gram[0][v][c][t];
    const float* __restrict__ G1 = g_gram[1][v][c][t];
    const float* __restrict__ G2 = g_gram[2][v][c][t];
    float inv_nm1 = 1.f / (fn - 1.f);
    float wgt_tile = diag ? 1.f : 2.f;

    float sum = 0.f;
    #pragma unroll
    for (int k = 0; k < 16; k++) {
        int idx = tid + k * 256;
        int r = idx >> 6, col = idx & 63;
        float cv = (G0[idx] + G1[idx] + G2[idx] - fn * mi[r] * mj[col]) * inv_nm1;
        float w = (diag && r == col) ? 0.f : wgt_tile;
        sum += w * cv * cv;
    }
    sum = block_reduce_256(sum, red);
    if (tid == 0) g_cov_partial[(v * C_CLASSES + c) * N_TILES + t] = sum;
}

// ---------------- K6: finalize all terms (mean/var on the fly) --------------
__constant__ int c_diagt[4] = {0, 4, 7, 9};

__global__ void k6_final(float* __restrict__ out, int N) {
    __shared__ float m[C_CLASSES * D_DIM];
    __shared__ float red[256];
    int tid = threadIdx.x;

    // mean/var on the fly: entry e = v*4096 + c*256 + d; both views of a
    // given (c,d) land on the same thread (v=0 iterations first).
    float vsum = 0.f;
    for (int e = tid; e < 2 * C_CLASSES * D_DIM; e += 256) {
        int d = e & (D_DIM - 1);
        int c = (e >> 8) & (C_CLASSES - 1);
        int v = e >> 12;
        float fn = (float)g_counts[c];
        float colsum = 0.f, Gdd = 0.f;
        int s = d >> 6, dd = d & 63;
        #pragma unroll
        for (int sl = 0; sl < KSPLIT; sl++) {
            colsum += g_colsum[sl][v][c][d];
            Gdd    += g_gram[sl][v][c][c_diagt[s]][dd * 64 + dd];
        }
        float mean = colsum / fn;
        float var  = (Gdd - fn * mean * mean) / (fn - 1.f);
        vsum += fmaxf(0.f, 1.f - sqrtf(var + EPS_V));
        int mc = c * D_DIM + d;
        if (v == 0) m[mc] = 0.5f * mean;
        else        m[mc] += 0.5f * mean;
    }
    __syncthreads();
    vsum = block_reduce_256(vsum, red);

    // invariance partials
    float inv_sum = 0.f;
    for (int e = tid; e < CVT_BLOCKS; e += 256) inv_sum += g_inv_partial[e];
    inv_sum = block_reduce_256(inv_sum, red);

    // covariance
    float csum = 0.f;
    for (int e = tid; e < 2 * C_CLASSES * N_TILES; e += 256)
        csum += g_cov_partial[e];
    csum = block_reduce_256(csum, red);

    // class-discriminative margin (120 pairs)
    float psum = 0.f;
    const int npairs = C_CLASSES * (C_CLASSES - 1) / 2;
    if (tid < npairs) {
        int i = 0, rem = tid;
        while (rem >= C_CLASSES - 1 - i) { rem -= C_CLASSES - 1 - i; i++; }
        int j = i + 1 + rem;
        float d2 = 0.f;
        for (int d = 0; d < D_DIM; d++) {
            float df = m[i * D_DIM + d] - m[j * D_DIM + d];
            d2 += df * df;
        }
        float dist = sqrtf(d2);
        float rr = fmaxf(0.f, ALPHA - dist);
        psum = rr * rr;
    }
    psum = block_reduce_256(psum, red);

    if (tid == 0) {
        float inv_loss   = inv_sum / ((float)N * (float)D_DIM);
        float var_loss   = vsum * 0.5f / ((float)C_CLASSES * (float)D_DIM);
        float cov_loss   = csum * 0.5f / ((float)C_CLASSES * (float)D_DIM);
        float class_loss = psum / (float)npairs;
        out[0] = LAM * inv_loss + MU * var_loss + NU * cov_loss + ALPHA * class_loss;
    }
}

// ---------------- launch -----------------------------------------------------
extern "C" void kernel_launch(void* const* d_in, const int* in_sizes, int n_in,
                              void* d_out, int out_size) {
    const float* za     = (const float*)d_in[0];
    const float* zb     = (const float*)d_in[1];
    const int*   labels = (const int*)d_in[2];
    int N = in_sizes[2];   // labels element count

    k1_hist<<<NCHUNK / 8, 256>>>(labels, N);
    k2_scan<<<1, 512>>>();
    k1b_cvt<<<NCHUNK, 256>>>(za, zb, N);
    k5_gram<<<dim3(N_PAIRS * KSPLIT, C_CLASSES, 2), 128>>>();
    k5c_cov<<<dim3(N_TILES, C_CLASSES, 2), 256>>>();
    k6_final<<<1, 256>>>((float*)d_out, N);
}